// round 6
// baseline (speedup 1.0000x reference)
#include <cuda_runtime.h>
#include <math.h>

#define B_   64
#define T_   256
#define D_   512
#define U_   512
#define G3   1536   // 3*U
#define GHC  4      // partial k-chunks for recurrence

typedef unsigned long long ull;

// ---------------- device scratch (static: no runtime allocation) ----------
__device__ float g_GX[2][T_][B_][G3];      // e@W + b_in, per direction
__device__ float g_GHp[GHC][2][B_][G3];    // k-chunk partial sums of h@Uw
__device__ float g_H[2][B_][U_];           // hidden state

// per-direction barrier state, padded to separate cache lines
struct __align__(128) BarState { unsigned int count; unsigned int gen; unsigned int pad[30]; };
__device__ BarState g_bar[2];

// ---------------- f32x2 packed helpers ------------------------------------
__device__ __forceinline__ void fma2(ull& d, ull a, ull b) {
    asm("fma.rn.f32x2 %0, %1, %2, %3;" : "=l"(d) : "l"(a), "l"(b), "l"(d));
}
__device__ __forceinline__ ull dup2(float v) {
    ull r; asm("mov.b64 %0, {%1, %1};" : "=l"(r) : "f"(v)); return r;
}
__device__ __forceinline__ float2 unpk(ull v) {
    float2 f; asm("mov.b64 {%0, %1}, %2;" : "=f"(f.x), "=f"(f.y) : "l"(v)); return f;
}

// ---------------- software barrier over one direction's 64 blocks ---------
// (identical logic to the proven R2/R4/R5 barrier, per-dir state)
__device__ __forceinline__ void dir_sync(int dir, unsigned nb) {
    volatile unsigned* vgen = (volatile unsigned*)&g_bar[dir].gen;
    __syncthreads();
    if (threadIdx.x == 0) {
        unsigned gen = *vgen;
        __threadfence();                       // order gen-read & prior stores before arrive
        if (atomicAdd(&g_bar[dir].count, 1u) == nb - 1u) {
            g_bar[dir].count = 0u;
            __threadfence();
            atomicAdd(&g_bar[dir].gen, 1u);
        } else {
            while (*vgen == gen) { __nanosleep(64); }
        }
        __threadfence();                       // acquire
    }
    __syncthreads();
}

// ======================================================================
// Kernel 1: GX[dir][t][b][:] = emb[x[b][t]] @ W_dir + b_in
// Tile 64 rows (batch @ fixed t) x 128 cols, BK=16, per-thread 4x8 via f32x2
// ======================================================================
__global__ __launch_bounds__(256)
void k_input_gemm(const int* __restrict__ x,
                  const float* __restrict__ emb,
                  const float* __restrict__ Wf,
                  const float* __restrict__ bf,
                  const float* __restrict__ Wb,
                  const float* __restrict__ bb)
{
    const int jt  = blockIdx.x;     // 0..11 (col tile of 128)
    const int t   = blockIdx.y;     // 0..255
    const int dir = blockIdx.z;
    const float* __restrict__ W   = dir ? Wb : Wf;
    const float* __restrict__ bin = dir ? bb : bf;   // row 0 = input bias

    __shared__ float As_t[16][68];   // [k][row] transposed, padded
    __shared__ float Bs[16][128];    // [k][col]
    __shared__ int   tok[64];

    const int tid = threadIdx.x;
    if (tid < 64) tok[tid] = x[tid * T_ + t];
    __syncthreads();

    const int tx = tid & 15;         // col group (8 cols)
    const int ty = tid >> 4;         // row group (4 rows)
    const int j0 = jt * 128;

    ull acc[4][4];
#pragma unroll
    for (int r = 0; r < 4; ++r)
#pragma unroll
        for (int c = 0; c < 4; ++c) acc[r][c] = 0ull;

    for (int k0 = 0; k0 < D_; k0 += 16) {
        // A tile (embedding gather), transposed
        {
            int li = tid * 4;
            int i  = li >> 4;            // row 0..63
            int kb = li & 15;            // 0,4,8,12
            float4 v = *(const float4*)&emb[(size_t)tok[i] * D_ + k0 + kb];
            As_t[kb + 0][i] = v.x;
            As_t[kb + 1][i] = v.y;
            As_t[kb + 2][i] = v.z;
            As_t[kb + 3][i] = v.w;
        }
        // B tile: 2048 floats, 2 float4 per thread
#pragma unroll
        for (int r = 0; r < 2; ++r) {
            int li = tid + r * 256;      // float4 units
            int k  = li >> 5;            // 0..15
            int j  = (li & 31) * 4;      // 0..124
            *(float4*)&Bs[k][j] = *(const float4*)&W[(size_t)(k0 + k) * G3 + j0 + j];
        }
        __syncthreads();
#pragma unroll
        for (int k = 0; k < 16; ++k) {
            float4 a4 = *(const float4*)&As_t[k][ty * 4];
            const ull* bp = (const ull*)&Bs[k][tx * 8];
            ull b0 = bp[0], b1 = bp[1], b2 = bp[2], b3 = bp[3];
            ull a0 = dup2(a4.x), a1 = dup2(a4.y), a2 = dup2(a4.z), a3 = dup2(a4.w);
            fma2(acc[0][0], a0, b0); fma2(acc[0][1], a0, b1); fma2(acc[0][2], a0, b2); fma2(acc[0][3], a0, b3);
            fma2(acc[1][0], a1, b0); fma2(acc[1][1], a1, b1); fma2(acc[1][2], a1, b2); fma2(acc[1][3], a1, b3);
            fma2(acc[2][0], a2, b0); fma2(acc[2][1], a2, b1); fma2(acc[2][2], a2, b2); fma2(acc[2][3], a2, b3);
            fma2(acc[3][0], a3, b0); fma2(acc[3][1], a3, b1); fma2(acc[3][2], a3, b2); fma2(acc[3][3], a3, b3);
        }
        __syncthreads();
    }

    // epilogue: add input bias, store
    const int j = j0 + tx * 8;
    float4 bi0 = *(const float4*)&bin[j];
    float4 bi1 = *(const float4*)&bin[j + 4];
#pragma unroll
    for (int r = 0; r < 4; ++r) {
        int b = ty * 4 + r;
        float2 p0 = unpk(acc[r][0]), p1 = unpk(acc[r][1]);
        float2 p2 = unpk(acc[r][2]), p3 = unpk(acc[r][3]);
        float4 o0 = make_float4(p0.x + bi0.x, p0.y + bi0.y, p1.x + bi0.z, p1.y + bi0.w);
        float4 o1 = make_float4(p2.x + bi1.x, p2.y + bi1.y, p3.x + bi1.z, p3.y + bi1.w);
        *(float4*)&g_GX[dir][t][b][j]     = o0;
        *(float4*)&g_GX[dir][t][b][j + 4] = o1;
    }
}

// ======================================================================
// Kernel 2: persistent bidirectional GRU recurrence.
// 128 blocks = dir(2) x batch-tile(2 of 32) x unit-tile(8 of 64) x k-chunk(4 of 128)
// Per-direction 64-block barriers (directions fully decoupled).
// Phase A identical to R5 (packed f32x2, persistent smem Uw).
// Phase B: per-dir mapping, block handles batch b=bid&63, units u=2*tid(+1),
//          float2-vectorized loads, __expf fast gate math.
// ======================================================================
__global__ __launch_bounds__(256, 1)
void k_recurrence(const int* __restrict__ x,
                  const float* __restrict__ Uf,
                  const float* __restrict__ Ub,
                  const float* __restrict__ bf,
                  const float* __restrict__ bb,
                  float* __restrict__ out)
{
    extern __shared__ float smem_f[];
    float* h_s = smem_f;                 // [32][128]
    float* u_s = smem_f + 32 * 128;      // [128][192]  (k-major, gate*64+unit)

    const int bid = blockIdx.x;     // 0..127
    const int tid = threadIdx.x;    // 0..255
    const int kc  = bid & 3;
    const int ut  = (bid >> 2) & 7;
    const int bt  = (bid >> 5) & 1;
    const int dir = bid >> 6;
    const int b0 = bt * 32, u0 = ut * 64, k0 = kc * 128;
    const float* __restrict__ Uw = dir ? Ub : Uf;

    // persistent Uw slice: u_s[k*192 + g*64 + q] = Uw[(k0+k)*G3 + g*512 + u0 + q]
    for (int v = tid; v < 128 * 48; v += 256) {          // float4 granules
        int k   = v / 48;
        int rem = v - k * 48;
        int g   = rem >> 4;
        int q   = (rem & 15) * 4;
        *(float4*)&u_s[k * 192 + g * 64 + q] =
            *(const float4*)&Uw[(size_t)(k0 + k) * G3 + g * 512 + u0 + q];
    }

    // init H = 0 (per dir: 8 blocks with ut==0 cover bt(2) x kc(4))
    if (ut == 0) {
        for (int j = tid; j < 32 * 128; j += 256) {
            int b = j >> 7, k = j & 127;
            g_H[dir][b0 + b][k0 + k] = 0.f;
        }
    }
    dir_sync(dir, 64);

    const int tu = tid & 31;     // unit pair: u0 + 2*tu, +1
    const int tb = tid >> 5;     // batch quad: b0 + 4*tb ..

    // phase-B constants (per-dir mapping: this block owns batch bB, all 512 units)
    const int bB = bid & 63;                               // batch 0..63
    const float* __restrict__ brr = (dir ? bb : bf) + G3;  // recurrent bias row
    const float2 bz = *(const float2*)&brr[2 * tid];
    const float2 br = *(const float2*)&brr[512 + 2 * tid];
    const float2 bh = *(const float2*)&brr[1024 + 2 * tid];

    float* __restrict__ state = out + (size_t)B_ * T_ * 1024;

    for (int s = 0; s < T_; ++s) {
        // ---- stage h (global -> smem) ------------------------------------
        for (int j4 = tid; j4 < 1024; j4 += 256) {
            int b  = j4 >> 5;
            int kv = (j4 & 31) * 4;
            float4 v = __ldcg((const float4*)&g_H[dir][b0 + b][k0 + kv]);
            *(float4*)&h_s[b * 128 + kv] = v;
        }
        __syncthreads();

        // ---- phase A: partial gh = h @ Uw (packed f32x2) ------------------
        ull acc[3][4];
#pragma unroll
        for (int g = 0; g < 3; ++g)
#pragma unroll
            for (int i = 0; i < 4; ++i) acc[g][i] = 0ull;

#pragma unroll 4
        for (int kk = 0; kk < 128; ++kk) {
            ull h0v = dup2(h_s[(tb * 4 + 0) * 128 + kk]);
            ull h1v = dup2(h_s[(tb * 4 + 1) * 128 + kk]);
            ull h2v = dup2(h_s[(tb * 4 + 2) * 128 + kk]);
            ull h3v = dup2(h_s[(tb * 4 + 3) * 128 + kk]);
            const float* ur = &u_s[kk * 192 + 2 * tu];
            ull w0 = *(const ull*)(ur);          // gate z
            ull w1 = *(const ull*)(ur + 64);     // gate r
            ull w2 = *(const ull*)(ur + 128);    // gate h
            fma2(acc[0][0], h0v, w0); fma2(acc[0][1], h1v, w0);
            fma2(acc[0][2], h2v, w0); fma2(acc[0][3], h3v, w0);
            fma2(acc[1][0], h0v, w1); fma2(acc[1][1], h1v, w1);
            fma2(acc[1][2], h2v, w1); fma2(acc[1][3], h3v, w1);
            fma2(acc[2][0], h0v, w2); fma2(acc[2][1], h1v, w2);
            fma2(acc[2][2], h2v, w2); fma2(acc[2][3], h3v, w2);
        }
        __syncthreads();   // h_s reads done before next step's staging

        // store partials
#pragma unroll
        for (int g = 0; g < 3; ++g)
#pragma unroll
            for (int i = 0; i < 4; ++i) {
                int b = b0 + tb * 4 + i;
                float2 w = unpk(acc[g][i]);
                __stcg((float2*)&g_GHp[kc][dir][b][g * 512 + u0 + 2 * tu], w);
            }
        dir_sync(dir, 64);

        // ---- phase B: gates + state update + output (this dir only) ------
        {
            const int t = dir ? (T_ - 1 - s) : s;
            const bool m = (x[bB * T_ + t] != 0);
            const int u = 2 * tid;

            float2 gz = bz, gr = br, gh = bh;
#pragma unroll
            for (int c = 0; c < GHC; ++c) {
                float2 a = __ldcg((const float2*)&g_GHp[c][dir][bB][u]);
                float2 b2 = __ldcg((const float2*)&g_GHp[c][dir][bB][512 + u]);
                float2 c2 = __ldcg((const float2*)&g_GHp[c][dir][bB][1024 + u]);
                gz.x += a.x;  gz.y += a.y;
                gr.x += b2.x; gr.y += b2.y;
                gh.x += c2.x; gh.y += c2.y;
            }
            const float* __restrict__ gx = &g_GX[dir][t][bB][0];
            float2 xz = *(const float2*)&gx[u];
            float2 xr = *(const float2*)&gx[512 + u];
            float2 xh = *(const float2*)&gx[1024 + u];
            float2 hold = __ldcg((const float2*)&g_H[dir][bB][u]);

            float2 hn;
            {
                float z  = __fdividef(1.f, 1.f + __expf(-(xz.x + gz.x)));
                float rr = __fdividef(1.f, 1.f + __expf(-(xr.x + gr.x)));
                float a  = xh.x + rr * gh.x;
                float hc = 1.f - __fdividef(2.f, 1.f + __expf(2.f * a));  // tanh(a)
                hn.x = z * hold.x + (1.f - z) * hc;
                hn.x = m ? hn.x : hold.x;
            }
            {
                float z  = __fdividef(1.f, 1.f + __expf(-(xz.y + gz.y)));
                float rr = __fdividef(1.f, 1.f + __expf(-(xr.y + gr.y)));
                float a  = xh.y + rr * gh.y;
                float hc = 1.f - __fdividef(2.f, 1.f + __expf(2.f * a));  // tanh(a)
                hn.y = z * hold.y + (1.f - z) * hc;
                hn.y = m ? hn.y : hold.y;
            }

            __stcg((float2*)&g_H[dir][bB][u], hn);
            *(float2*)&out[((size_t)bB * T_ + t) * 1024 + dir * 512 + u] = hn;  // out_t == h_t
            if (s == T_ - 1)
                *(float2*)&state[(size_t)bB * 1024 + dir * 512 + u] = hn;
        }
        dir_sync(dir, 64);
    }
}

// ======================================================================
// Kernel 3: LayerNorm over last dim (1024) of out, in place
// ======================================================================
__global__ __launch_bounds__(256)
void k_layernorm(float* __restrict__ out,
                 const float* __restrict__ gamma,
                 const float* __restrict__ beta)
{
    const int row = blockIdx.x;                 // 0..16383
    float* p = out + (size_t)row * 1024;
    const int tid = threadIdx.x;

    float4 v = *(const float4*)&p[tid * 4];
    float s = v.x + v.y + v.z + v.w;
    float q = v.x * v.x + v.y * v.y + v.z * v.z + v.w * v.w;
#pragma unroll
    for (int o = 16; o; o >>= 1) {
        s += __shfl_xor_sync(0xFFFFFFFFu, s, o);
        q += __shfl_xor_sync(0xFFFFFFFFu, q, o);
    }
    __shared__ float ss[8], qq[8];
    __shared__ float mean_s, rstd_s;
    if ((tid & 31) == 0) { ss[tid >> 5] = s; qq[tid >> 5] = q; }
    __syncthreads();
    if (tid == 0) {
        float S = 0.f, Q = 0.f;
#pragma unroll
        for (int i = 0; i < 8; ++i) { S += ss[i]; Q += qq[i]; }
        float mean = S * (1.f / 1024.f);
        float var  = Q * (1.f / 1024.f) - mean * mean;
        mean_s = mean;
        rstd_s = rsqrtf(var + 1e-3f);
    }
    __syncthreads();
    float mean = mean_s, rstd = rstd_s;
    float4 g  = *(const float4*)&gamma[tid * 4];
    float4 be = *(const float4*)&beta[tid * 4];
    v.x = (v.x - mean) * rstd * g.x + be.x;
    v.y = (v.y - mean) * rstd * g.y + be.y;
    v.z = (v.z - mean) * rstd * g.z + be.z;
    v.w = (v.w - mean) * rstd * g.w + be.w;
    *(float4*)&p[tid * 4] = v;
}

// ======================================================================
extern "C" void kernel_launch(void* const* d_in, const int* in_sizes, int n_in,
                              void* d_out, int out_size)
{
    const int*   x     = (const int*)  d_in[0];
    const float* emb   = (const float*)d_in[1];
    const float* Wf    = (const float*)d_in[2];
    const float* Uf    = (const float*)d_in[3];
    const float* bf    = (const float*)d_in[4];
    const float* Wb    = (const float*)d_in[5];
    const float* Ub    = (const float*)d_in[6];
    const float* bb    = (const float*)d_in[7];
    const float* gamma = (const float*)d_in[8];
    const float* beta  = (const float*)d_in[9];
    float* out = (float*)d_out;

    const int smem2 = 32 * 128 * 4 + 128 * 192 * 4;   // 16KB h_s + 96KB Uw = 112KB
    cudaFuncSetAttribute(k_recurrence, cudaFuncAttributeMaxDynamicSharedMemorySize, smem2);

    dim3 g1(G3 / 128, T_, 2);
    k_input_gemm<<<g1, 256>>>(x, emb, Wf, bf, Wb, bb);
    k_recurrence<<<128, 256, smem2>>>(x, Uf, Ub, bf, bb, out);
    k_layernorm<<<B_ * T_, 256>>>(out, gamma, beta);
}

// round 7
// speedup vs baseline: 1.0908x; 1.0908x over previous
#include <cuda_runtime.h>
#include <math.h>

#define B_   64
#define T_   256
#define D_   512
#define U_   512
#define G3   1536   // 3*U
#define GHC  8      // partial k-chunks for recurrence (4 kc x 2 khalf)

typedef unsigned long long ull;

// ---------------- device scratch (static: no runtime allocation) ----------
__device__ float g_GX[2][T_][B_][G3];      // e@W + b_in, per direction
__device__ float g_GHp[GHC][2][B_][G3];    // k-chunk partial sums of h@Uw
__device__ float g_H[2][B_][U_];           // hidden state

// per-direction barrier state, padded to separate cache lines
struct __align__(128) BarState { unsigned int count; unsigned int gen; unsigned int pad[30]; };
__device__ BarState g_bar[2];

// ---------------- f32x2 packed helpers ------------------------------------
__device__ __forceinline__ void fma2(ull& d, ull a, ull b) {
    asm("fma.rn.f32x2 %0, %1, %2, %3;" : "=l"(d) : "l"(a), "l"(b), "l"(d));
}
__device__ __forceinline__ ull dup2(float v) {
    ull r; asm("mov.b64 %0, {%1, %1};" : "=l"(r) : "f"(v)); return r;
}
__device__ __forceinline__ float2 unpk(ull v) {
    float2 f; asm("mov.b64 {%0, %1}, %2;" : "=f"(f.x), "=f"(f.y) : "l"(v)); return f;
}

// ---------------- software barrier over one direction's 64 blocks ---------
__device__ __forceinline__ void dir_sync(int dir, unsigned nb) {
    volatile unsigned* vgen = (volatile unsigned*)&g_bar[dir].gen;
    __syncthreads();
    if (threadIdx.x == 0) {
        unsigned gen = *vgen;
        __threadfence();                       // order gen-read & prior stores before arrive
        if (atomicAdd(&g_bar[dir].count, 1u) == nb - 1u) {
            g_bar[dir].count = 0u;
            __threadfence();
            atomicAdd(&g_bar[dir].gen, 1u);
        } else {
            while (*vgen == gen) { __nanosleep(64); }
        }
        __threadfence();                       // acquire
    }
    __syncthreads();
}

// ======================================================================
// Kernel 1: GX[dir][t][b][:] = emb[x[b][t]] @ W_dir + b_in
// (reverted to the proven scalar R2/R4/R5 version: 64-col tiles, BK=16)
// ======================================================================
__global__ __launch_bounds__(256)
void k_input_gemm(const int* __restrict__ x,
                  const float* __restrict__ emb,
                  const float* __restrict__ Wf,
                  const float* __restrict__ bf,
                  const float* __restrict__ Wb,
                  const float* __restrict__ bb)
{
    const int jt  = blockIdx.x;     // 0..23  (column tile)
    const int t   = blockIdx.y;     // 0..255
    const int dir = blockIdx.z;     // 0..1
    const float* __restrict__ W    = dir ? Wb : Wf;
    const float* __restrict__ bin  = dir ? bb : bf;   // row 0 = input bias

    __shared__ float As_t[16][68];   // [k][row] transposed A tile (padded)
    __shared__ float Bs[16][64];     // [k][col]
    __shared__ int   tok[64];

    const int tid = threadIdx.x;
    if (tid < 64) tok[tid] = x[tid * T_ + t];
    __syncthreads();

    const int tx = tid & 15;         // col group (4 cols)
    const int ty = tid >> 4;         // row group (4 rows)
    const int j0 = jt * 64;

    float acc[4][4];
#pragma unroll
    for (int r = 0; r < 4; ++r)
#pragma unroll
        for (int c = 0; c < 4; ++c) acc[r][c] = 0.f;

    for (int k0 = 0; k0 < D_; k0 += 16) {
        {
            int li = tid * 4;            // 0..1023
            int i  = li >> 4;            // row 0..63
            int kb = li & 15;            // 0,4,8,12
            float4 v = *(const float4*)&emb[(size_t)tok[i] * D_ + k0 + kb];
            As_t[kb + 0][i] = v.x;
            As_t[kb + 1][i] = v.y;
            As_t[kb + 2][i] = v.z;
            As_t[kb + 3][i] = v.w;
        }
        {
            int li = tid * 4;
            int k  = li >> 6;            // 0..15
            int j  = li & 63;
            float4 v = *(const float4*)&W[(size_t)(k0 + k) * G3 + j0 + j];
            *(float4*)&Bs[k][j] = v;
        }
        __syncthreads();
#pragma unroll
        for (int k = 0; k < 16; ++k) {
            float4 av = *(const float4*)&As_t[k][ty * 4];
            float4 bv = *(const float4*)&Bs[k][tx * 4];
            acc[0][0] += av.x * bv.x; acc[0][1] += av.x * bv.y; acc[0][2] += av.x * bv.z; acc[0][3] += av.x * bv.w;
            acc[1][0] += av.y * bv.x; acc[1][1] += av.y * bv.y; acc[1][2] += av.y * bv.z; acc[1][3] += av.y * bv.w;
            acc[2][0] += av.z * bv.x; acc[2][1] += av.z * bv.y; acc[2][2] += av.z * bv.z; acc[2][3] += av.z * bv.w;
            acc[3][0] += av.w * bv.x; acc[3][1] += av.w * bv.y; acc[3][2] += av.w * bv.z; acc[3][3] += av.w * bv.w;
        }
        __syncthreads();
    }

#pragma unroll
    for (int r = 0; r < 4; ++r) {
        int b = ty * 4 + r;
        int j = j0 + tx * 4;
        float4 o;
        o.x = acc[r][0] + bin[j + 0];
        o.y = acc[r][1] + bin[j + 1];
        o.z = acc[r][2] + bin[j + 2];
        o.w = acc[r][3] + bin[j + 3];
        *(float4*)&g_GX[dir][t][b][j] = o;
    }
}

// ======================================================================
// Kernel 2: persistent bidirectional GRU recurrence.
// 128 blocks = dir(2) x batch-tile(2 of 32) x unit-tile(8 of 64) x k-chunk(4 of 128)
// Per-direction 64-block barriers. Uw slice persistent in smem.
// Phase A remap (this round): warp w -> batch octet (w&3), K half (w>>2);
//   each thread: 2 units x 8 batches x 3 gates over 64 kk -> 2x weight reuse,
//   GHp now has 8 partial chunks.
// Phase B: per-dir mapping (R6), GHC=8 reduction, fast gate math.
// ======================================================================
__global__ __launch_bounds__(256, 1)
void k_recurrence(const int* __restrict__ x,
                  const float* __restrict__ Uf,
                  const float* __restrict__ Ub,
                  const float* __restrict__ bf,
                  const float* __restrict__ bb,
                  float* __restrict__ out)
{
    extern __shared__ float smem_f[];
    float* h_s = smem_f;                 // [32][128]
    float* u_s = smem_f + 32 * 128;      // [128][192]  (k-major, gate*64+unit)

    const int bid = blockIdx.x;     // 0..127
    const int tid = threadIdx.x;    // 0..255
    const int kc  = bid & 3;
    const int ut  = (bid >> 2) & 7;
    const int bt  = (bid >> 5) & 1;
    const int dir = bid >> 6;
    const int b0 = bt * 32, u0 = ut * 64, k0 = kc * 128;
    const float* __restrict__ Uw = dir ? Ub : Uf;

    // persistent Uw slice: u_s[k*192 + g*64 + q] = Uw[(k0+k)*G3 + g*512 + u0 + q]
    for (int v = tid; v < 128 * 48; v += 256) {          // float4 granules
        int k   = v / 48;
        int rem = v - k * 48;
        int g   = rem >> 4;
        int q   = (rem & 15) * 4;
        *(float4*)&u_s[k * 192 + g * 64 + q] =
            *(const float4*)&Uw[(size_t)(k0 + k) * G3 + g * 512 + u0 + q];
    }

    // init H = 0 (per dir: 8 blocks with ut==0 cover bt(2) x kc(4))
    if (ut == 0) {
        for (int j = tid; j < 32 * 128; j += 256) {
            int b = j >> 7, k = j & 127;
            g_H[dir][b0 + b][k0 + k] = 0.f;
        }
    }
    dir_sync(dir, 64);

    // ---- phase-A thread mapping ----
    const int warp  = tid >> 5;
    const int lane  = tid & 31;          // unit pair: u0 + 2*lane, +1
    const int khalf = warp >> 2;         // 0..1   (kk range)
    const int wb    = warp & 3;          // batch octet: b0 + wb*8 ..
    const int kbeg  = khalf * 64;
    const int chunk = kc + 4 * khalf;    // GHp chunk 0..7

    // phase-B constants (per-dir mapping: this block owns batch bB, all 512 units)
    const int bB = bid & 63;                               // batch 0..63
    const float* __restrict__ brr = (dir ? bb : bf) + G3;  // recurrent bias row
    const float2 bz = *(const float2*)&brr[2 * tid];
    const float2 br = *(const float2*)&brr[512 + 2 * tid];
    const float2 bh = *(const float2*)&brr[1024 + 2 * tid];

    float* __restrict__ state = out + (size_t)B_ * T_ * 1024;

    for (int s = 0; s < T_; ++s) {
        // ---- stage h (global -> smem) ------------------------------------
        for (int j4 = tid; j4 < 1024; j4 += 256) {
            int b  = j4 >> 5;
            int kv = (j4 & 31) * 4;
            float4 v = __ldcg((const float4*)&g_H[dir][b0 + b][k0 + kv]);
            *(float4*)&h_s[b * 128 + kv] = v;
        }
        __syncthreads();

        // ---- phase A: partial gh = h @ Uw (f32x2, 8-batch weight reuse) ---
        ull acc[3][8];
#pragma unroll
        for (int g = 0; g < 3; ++g)
#pragma unroll
            for (int i = 0; i < 8; ++i) acc[g][i] = 0ull;

        const float* hbase = &h_s[(wb * 8) * 128];
#pragma unroll 4
        for (int kk = kbeg; kk < kbeg + 64; ++kk) {
            const float* ur = &u_s[kk * 192 + 2 * lane];
            ull w0 = *(const ull*)(ur);          // gate z, units 2*lane..+1
            ull w1 = *(const ull*)(ur + 64);     // gate r
            ull w2 = *(const ull*)(ur + 128);    // gate h
#pragma unroll
            for (int i = 0; i < 8; ++i) {
                ull hv = dup2(hbase[i * 128 + kk]);
                fma2(acc[0][i], hv, w0);
                fma2(acc[1][i], hv, w1);
                fma2(acc[2][i], hv, w2);
            }
        }
        __syncthreads();   // h_s reads done before next step's staging

        // store partials
#pragma unroll
        for (int g = 0; g < 3; ++g)
#pragma unroll
            for (int i = 0; i < 8; ++i) {
                int b = b0 + wb * 8 + i;
                float2 w = unpk(acc[g][i]);
                __stcg((float2*)&g_GHp[chunk][dir][b][g * 512 + u0 + 2 * lane], w);
            }
        dir_sync(dir, 64);

        // ---- phase B: gates + state update + output (this dir only) ------
        {
            const int t = dir ? (T_ - 1 - s) : s;
            const bool m = (x[bB * T_ + t] != 0);
            const int u = 2 * tid;

            float2 gz = bz, gr = br, gh = bh;
#pragma unroll
            for (int c = 0; c < GHC; ++c) {
                float2 a  = __ldcg((const float2*)&g_GHp[c][dir][bB][u]);
                float2 b2 = __ldcg((const float2*)&g_GHp[c][dir][bB][512 + u]);
                float2 c2 = __ldcg((const float2*)&g_GHp[c][dir][bB][1024 + u]);
                gz.x += a.x;  gz.y += a.y;
                gr.x += b2.x; gr.y += b2.y;
                gh.x += c2.x; gh.y += c2.y;
            }
            const float* __restrict__ gx = &g_GX[dir][t][bB][0];
            float2 xz = *(const float2*)&gx[u];
            float2 xr = *(const float2*)&gx[512 + u];
            float2 xh = *(const float2*)&gx[1024 + u];
            float2 hold = __ldcg((const float2*)&g_H[dir][bB][u]);

            float2 hn;
            {
                float z  = __fdividef(1.f, 1.f + __expf(-(xz.x + gz.x)));
                float rr = __fdividef(1.f, 1.f + __expf(-(xr.x + gr.x)));
                float a  = xh.x + rr * gh.x;
                float hc = 1.f - __fdividef(2.f, 1.f + __expf(2.f * a));  // tanh(a)
                hn.x = z * hold.x + (1.f - z) * hc;
                hn.x = m ? hn.x : hold.x;
            }
            {
                float z  = __fdividef(1.f, 1.f + __expf(-(xz.y + gz.y)));
                float rr = __fdividef(1.f, 1.f + __expf(-(xr.y + gr.y)));
                float a  = xh.y + rr * gh.y;
                float hc = 1.f - __fdividef(2.f, 1.f + __expf(2.f * a));  // tanh(a)
                hn.y = z * hold.y + (1.f - z) * hc;
                hn.y = m ? hn.y : hold.y;
            }

            __stcg((float2*)&g_H[dir][bB][u], hn);
            *(float2*)&out[((size_t)bB * T_ + t) * 1024 + dir * 512 + u] = hn;  // out_t == h_t
            if (s == T_ - 1)
                *(float2*)&state[(size_t)bB * 1024 + dir * 512 + u] = hn;
        }
        dir_sync(dir, 64);
    }
}

// ======================================================================
// Kernel 3: LayerNorm over last dim (1024) of out, in place
// ======================================================================
__global__ __launch_bounds__(256)
void k_layernorm(float* __restrict__ out,
                 const float* __restrict__ gamma,
                 const float* __restrict__ beta)
{
    const int row = blockIdx.x;                 // 0..16383
    float* p = out + (size_t)row * 1024;
    const int tid = threadIdx.x;

    float4 v = *(const float4*)&p[tid * 4];
    float s = v.x + v.y + v.z + v.w;
    float q = v.x * v.x + v.y * v.y + v.z * v.z + v.w * v.w;
#pragma unroll
    for (int o = 16; o; o >>= 1) {
        s += __shfl_xor_sync(0xFFFFFFFFu, s, o);
        q += __shfl_xor_sync(0xFFFFFFFFu, q, o);
    }
    __shared__ float ss[8], qq[8];
    __shared__ float mean_s, rstd_s;
    if ((tid & 31) == 0) { ss[tid >> 5] = s; qq[tid >> 5] = q; }
    __syncthreads();
    if (tid == 0) {
        float S = 0.f, Q = 0.f;
#pragma unroll
        for (int i = 0; i < 8; ++i) { S += ss[i]; Q += qq[i]; }
        float mean = S * (1.f / 1024.f);
        float var  = Q * (1.f / 1024.f) - mean * mean;
        mean_s = mean;
        rstd_s = rsqrtf(var + 1e-3f);
    }
    __syncthreads();
    float mean = mean_s, rstd = rstd_s;
    float4 g  = *(const float4*)&gamma[tid * 4];
    float4 be = *(const float4*)&beta[tid * 4];
    v.x = (v.x - mean) * rstd * g.x + be.x;
    v.y = (v.y - mean) * rstd * g.y + be.y;
    v.z = (v.z - mean) * rstd * g.z + be.z;
    v.w = (v.w - mean) * rstd * g.w + be.w;
    *(float4*)&p[tid * 4] = v;
}

// ======================================================================
extern "C" void kernel_launch(void* const* d_in, const int* in_sizes, int n_in,
                              void* d_out, int out_size)
{
    const int*   x     = (const int*)  d_in[0];
    const float* emb   = (const float*)d_in[1];
    const float* Wf    = (const float*)d_in[2];
    const float* Uf    = (const float*)d_in[3];
    const float* bf    = (const float*)d_in[4];
    const float* Wb    = (const float*)d_in[5];
    const float* Ub    = (const float*)d_in[6];
    const float* bb    = (const float*)d_in[7];
    const float* gamma = (const float*)d_in[8];
    const float* beta  = (const float*)d_in[9];
    float* out = (float*)d_out;

    const int smem2 = 32 * 128 * 4 + 128 * 192 * 4;   // 16KB h_s + 96KB Uw = 112KB
    cudaFuncSetAttribute(k_recurrence, cudaFuncAttributeMaxDynamicSharedMemorySize, smem2);

    dim3 g1(G3 / 64, T_, 2);
    k_input_gemm<<<g1, 256>>>(x, emb, Wf, bf, Wb, bb);
    k_recurrence<<<128, 256, smem2>>>(x, Uf, Ub, bf, bb, out);
    k_layernorm<<<B_ * T_, 256>>>(out, gamma, beta);
}